// round 5
// baseline (speedup 1.0000x reference)
#include <cuda_runtime.h>
#include <cuda_bf16.h>
#include <math.h>

#define TWO_PI_F 6.283185307179586f
#define EPS_F 1e-8f

// -------- device scratch (no allocation allowed) --------
__device__ float g_inv[64 * 64];
__device__ float g_det;
__device__ int   g_notident;   // 0 => Sigma == I (fast path valid); set by fast kernel

// ============================================================
// Fast path (speculative): computes q = ||x - mu||^2, det = 1.
// Runs unconditionally; correct whenever Sigma == I.
// The first 2 lanes of blocks 0..511 verify one float4 of Sigma
// each (16 KB total, amortized in the kernel's own memory stream)
// and set g_notident on mismatch. If set, later kernels recompute.
//
// One warp handles 8 samples (2048 contiguous bytes = 128 float4):
//   lane l loads float4 #(l + 32*j), j = 0..3  (front-batched, MLP=4).
//   float4 f belongs to sample f/16 => load j of lane l belongs to
//   sample s0 + 2*j + (l>>4).
// 16-lane butterfly reduction over hl = l&15; lanes 0 and 16 write
// 4 outputs each.
// ============================================================
__global__ __launch_bounds__(256)
void nll_identity_kernel(const float* __restrict__ samples,
                         const float* __restrict__ Phi,
                         const float* __restrict__ mu,
                         const float* __restrict__ Sigma,
                         float* __restrict__ out, int N) {
    // distributed Sigma identity check: blocks 0..511, first 2 lanes of
    // warp 0 each check one float4 (512 * 2 * 4 = 4096 elements)
    if (threadIdx.x < 2 && blockIdx.x < 512) {
        const int f = blockIdx.x * 2 + threadIdx.x;     // float4 index 0..1023
        const float4 v = reinterpret_cast<const float4*>(Sigma)[f];
        const int e0 = f * 4, e1 = f * 4 + 1, e2 = f * 4 + 2, e3 = f * 4 + 3;
        const float x0 = ((e0 >> 6) == (e0 & 63)) ? 1.0f : 0.0f;
        const float x1 = ((e1 >> 6) == (e1 & 63)) ? 1.0f : 0.0f;
        const float x2 = ((e2 >> 6) == (e2 & 63)) ? 1.0f : 0.0f;
        const float x3 = ((e3 >> 6) == (e3 & 63)) ? 1.0f : 0.0f;
        if (v.x != x0 || v.y != x1 || v.z != x2 || v.w != x3)
            atomicExch(&g_notident, 1);
    }

    const int warp = (blockIdx.x * blockDim.x + threadIdx.x) >> 5;
    const int lane = threadIdx.x & 31;
    const int s0   = warp * 8;
    if (s0 >= N) return;

    const float4* smp = reinterpret_cast<const float4*>(samples);
    const float4* mu4 = reinterpret_cast<const float4*>(mu);

    const int hl   = lane & 15;          // half-lane index 0..15
    const int base = s0 * 16;            // float4 index of chunk start

    // front-batch all 4 global loads (MLP_p1 = 4)
    float4 v0 = smp[base + lane];
    float4 v1 = smp[base + lane + 32];
    float4 v2 = smp[base + lane + 64];
    float4 v3 = smp[base + lane + 96];
    float4 m  = mu4[hl];

    float d;
    float a0, a1, a2, a3;
    d = v0.x - m.x; a0  = d * d;
    d = v0.y - m.y; a0 += d * d;
    d = v0.z - m.z; a0 += d * d;
    d = v0.w - m.w; a0 += d * d;

    d = v1.x - m.x; a1  = d * d;
    d = v1.y - m.y; a1 += d * d;
    d = v1.z - m.z; a1 += d * d;
    d = v1.w - m.w; a1 += d * d;

    d = v2.x - m.x; a2  = d * d;
    d = v2.y - m.y; a2 += d * d;
    d = v2.z - m.z; a2 += d * d;
    d = v2.w - m.w; a2 += d * d;

    d = v3.x - m.x; a3  = d * d;
    d = v3.y - m.y; a3 += d * d;
    d = v3.z - m.z; a3 += d * d;
    d = v3.w - m.w; a3 += d * d;

    #pragma unroll
    for (int off = 8; off >= 1; off >>= 1) {
        a0 += __shfl_xor_sync(0xffffffffu, a0, off);
        a1 += __shfl_xor_sync(0xffffffffu, a1, off);
        a2 += __shfl_xor_sync(0xffffffffu, a2, off);
        a3 += __shfl_xor_sync(0xffffffffu, a3, off);
    }

    if (hl == 0) {
        const float c  = Phi[0] * rsqrtf(TWO_PI_F);   // det == 1
        const int  sA  = s0 + (lane >> 4);            // lane0 -> s0, lane16 -> s0+1
        out[sA]     = -__logf(c * __expf(-0.5f * a0) + EPS_F);
        out[sA + 2] = -__logf(c * __expf(-0.5f * a1) + EPS_F);
        out[sA + 4] = -__logf(c * __expf(-0.5f * a2) + EPS_F);
        out[sA + 6] = -__logf(c * __expf(-0.5f * a3) + EPS_F);
    }
}

// ============================================================
// Prep (cold): only runs when Sigma != I. Gauss-Jordan inverse
// with partial pivoting + det into device scratch.
// On the hot path this is a flag read + return.
// ============================================================
__global__ __launch_bounds__(1024)
void prep_kernel(const float* __restrict__ Sigma) {
    if (g_notident == 0) return;

    __shared__ float A[64][129];   // augmented [Sigma | I], padded stride
    __shared__ float fcol[64];
    __shared__ float s_det;
    __shared__ int   s_piv;

    const int tid = threadIdx.x;
    const int bd  = blockDim.x;

    if (tid == 0) s_det = 1.0f;

    // build augmented matrix
    for (int i = tid; i < 64 * 64; i += bd) {
        int r = i >> 6, c = i & 63;
        A[r][c]      = Sigma[i];
        A[r][64 + c] = (r == c) ? 1.0f : 0.0f;
    }
    __syncthreads();

    for (int k = 0; k < 64; k++) {
        // partial pivot (single-thread scan; this path is cold)
        if (tid == 0) {
            int   p  = k;
            float mx = fabsf(A[k][k]);
            for (int i = k + 1; i < 64; i++) {
                float v = fabsf(A[i][k]);
                if (v > mx) { mx = v; p = i; }
            }
            s_piv = p;
        }
        __syncthreads();
        const int p = s_piv;
        if (p != k) {
            for (int c = tid; c < 128; c += bd) {
                float t = A[k][c]; A[k][c] = A[p][c]; A[p][c] = t;
            }
        }
        __syncthreads();
        const float piv = A[k][k];
        if (tid == 0) s_det *= (p != k) ? -piv : piv;
        const float rpiv = 1.0f / piv;
        for (int c = tid; c < 128; c += bd) A[k][c] *= rpiv;
        __syncthreads();
        // snapshot factors before elimination touches column k
        for (int r = tid; r < 64; r += bd) fcol[r] = A[r][k];
        __syncthreads();
        for (int idx = tid; idx < 64 * 128; idx += bd) {
            int r = idx >> 7, c = idx & 127;
            if (r != k) A[r][c] -= fcol[r] * A[k][c];
        }
        __syncthreads();
    }

    for (int i = tid; i < 64 * 64; i += bd) {
        int r = i >> 6, c = i & 63;
        g_inv[i] = A[r][64 + c];
    }
    if (tid == 0) g_det = s_det;
}

// ============================================================
// General fallback (cold): overwrites the speculative outputs
// when Sigma != I. On the hot path: flag read + return, with a
// small grid so the early-exit retire cost is ~1 us.
// ============================================================
__global__ __launch_bounds__(128)
void nll_general_kernel(const float* __restrict__ samples,
                        const float* __restrict__ Phi,
                        const float* __restrict__ mu,
                        float* __restrict__ out, int N) {
    if (g_notident == 0) return;

    __shared__ float M[64 * 64];
    for (int i = threadIdx.x; i < 64 * 64; i += blockDim.x) M[i] = g_inv[i];
    __syncthreads();

    const float det = g_det;
    const float c   = Phi[0] / sqrtf(TWO_PI_F * det);

    for (int n = blockIdx.x * blockDim.x + threadIdx.x; n < N;
         n += gridDim.x * blockDim.x) {
        float dv[64];
        #pragma unroll
        for (int i = 0; i < 64; i++) dv[i] = samples[n * 64 + i] - mu[i];
        float q = 0.0f;
        for (int r = 0; r < 64; r++) {
            float t = 0.0f;
            #pragma unroll
            for (int cc = 0; cc < 64; cc++) t += M[r * 64 + cc] * dv[cc];
            q += t * dv[r];
        }
        out[n] = -logf(c * expf(-0.5f * q) + EPS_F);
    }
}

extern "C" void kernel_launch(void* const* d_in, const int* in_sizes, int n_in,
                              void* d_out, int out_size) {
    const float* samples = (const float*)d_in[0];
    const float* Phi     = (const float*)d_in[1];
    const float* mu      = (const float*)d_in[2];
    const float* Sigma   = (const float*)d_in[3];
    float* out = (float*)d_out;

    const int N = out_size;  // number of samples

    // reset the mismatch flag every invocation (graph-capturable memset)
    void* flag_addr = nullptr;
    cudaGetSymbolAddress(&flag_addr, g_notident);
    cudaMemsetAsync(flag_addr, 0, sizeof(int));

    // speculative fast path + distributed Sigma check:
    // 8 samples per warp, 8 warps per block => 64 samples/block
    const int samples_per_block = 8 * 8;
    const int blocks = (N + samples_per_block - 1) / samples_per_block;
    nll_identity_kernel<<<blocks, 256>>>(samples, Phi, mu, Sigma, out, N);

    // cold path: inverse+det, then general recompute (both early-exit hot)
    prep_kernel<<<1, 1024>>>(Sigma);
    nll_general_kernel<<<296, 128>>>(samples, Phi, mu, out, N);
}

// round 7
// speedup vs baseline: 1.0394x; 1.0394x over previous
#include <cuda_runtime.h>
#include <cuda_bf16.h>
#include <math.h>

#define TWO_PI_F 6.283185307179586f
#define EPS_F 1e-8f

// -------- device scratch (no allocation allowed) --------
// g_notident: 0 => Sigma == I (fast path valid). Statically 0; only ever
// written (0 -> 1) when Sigma != I. Its value is a pure function of the
// input Sigma, so no per-invocation reset is needed (deterministic).
__device__ int g_notident = 0;

// ============================================================
// Fast path (speculative): q = ||x - mu||^2, det = 1.
// Runs unconditionally; correct whenever Sigma == I.
// First 2 lanes of blocks 0..511 verify one float4 of Sigma each
// (16 KB total, amortized inside the 260 MB stream) and set
// g_notident on mismatch; the fallback kernel then recomputes.
//
// One warp handles 16 samples (4096 contiguous bytes = 256 float4):
//   lane l front-batches float4 #(l + 32*j), j = 0..7 (MLP = 8).
//   float4 f belongs to sample f/16 => load j of lane l belongs to
//   sample s0 + 2*j + (l>>4).
// 16-lane butterfly reduction over hl = l&15; lanes 0 and 16 write
// 8 outputs each.
// ============================================================
__global__ __launch_bounds__(256)
void nll_identity_kernel(const float* __restrict__ samples,
                         const float* __restrict__ Phi,
                         const float* __restrict__ mu,
                         const float* __restrict__ Sigma,
                         float* __restrict__ out, int N) {
    // distributed Sigma identity check
    if (threadIdx.x < 2 && blockIdx.x < 512) {
        const int f = blockIdx.x * 2 + threadIdx.x;     // float4 index 0..1023
        const float4 v = reinterpret_cast<const float4*>(Sigma)[f];
        const int e0 = f * 4, e1 = f * 4 + 1, e2 = f * 4 + 2, e3 = f * 4 + 3;
        const float x0 = ((e0 >> 6) == (e0 & 63)) ? 1.0f : 0.0f;
        const float x1 = ((e1 >> 6) == (e1 & 63)) ? 1.0f : 0.0f;
        const float x2 = ((e2 >> 6) == (e2 & 63)) ? 1.0f : 0.0f;
        const float x3 = ((e3 >> 6) == (e3 & 63)) ? 1.0f : 0.0f;
        if (v.x != x0 || v.y != x1 || v.z != x2 || v.w != x3)
            atomicExch(&g_notident, 1);
    }

    const int warp = (blockIdx.x * blockDim.x + threadIdx.x) >> 5;
    const int lane = threadIdx.x & 31;
    const int s0   = warp * 16;
    if (s0 >= N) return;

    const float4* smp = reinterpret_cast<const float4*>(samples);
    const float4* mu4 = reinterpret_cast<const float4*>(mu);

    const int hl   = lane & 15;          // half-lane index 0..15
    const int base = s0 * 16;            // float4 index of chunk start

    const float c = Phi[0] * rsqrtf(TWO_PI_F);   // det == 1 on this path

    if (s0 + 16 <= N) {
        // front-batch all 8 global loads (MLP_p1 = 8)
        float4 v[8];
        #pragma unroll
        for (int j = 0; j < 8; j++) v[j] = smp[base + lane + 32 * j];
        float4 m = mu4[hl];

        float acc[8];
        #pragma unroll
        for (int j = 0; j < 8; j++) {
            float d;
            d = v[j].x - m.x; acc[j]  = d * d;
            d = v[j].y - m.y; acc[j] += d * d;
            d = v[j].z - m.z; acc[j] += d * d;
            d = v[j].w - m.w; acc[j] += d * d;
        }

        #pragma unroll
        for (int off = 8; off >= 1; off >>= 1) {
            #pragma unroll
            for (int j = 0; j < 8; j++)
                acc[j] += __shfl_xor_sync(0xffffffffu, acc[j], off);
        }

        if (hl == 0) {
            const int sA = s0 + (lane >> 4);     // lane0 -> s0, lane16 -> s0+1
            #pragma unroll
            for (int j = 0; j < 8; j++)
                out[sA + 2 * j] = -__logf(c * __expf(-0.5f * acc[j]) + EPS_F);
        }
    } else {
        // tail: scalar per-sample (cold; only when N % 16 != 0)
        for (int s = s0 + (lane >> 4); s < N; s += 2) {
            float partial = 0.0f;
            #pragma unroll
            for (int k = 0; k < 4; k++) {
                const int idx = s * 64 + hl * 4 + k;
                const float d = samples[idx] - mu[hl * 4 + k];
                partial += d * d;
            }
            float q = partial;
            #pragma unroll
            for (int off = 8; off >= 1; off >>= 1)
                q += __shfl_xor_sync(0xffffffffu, q, off);
            if (hl == 0)
                out[s] = -__logf(c * __expf(-0.5f * q) + EPS_F);
        }
    }
}

// ============================================================
// Fused fallback (cold): only does work when Sigma != I.
// Every block independently recomputes inv(Sigma) + det via
// Gauss-Jordan with partial pivoting in its own shared memory
// (redundant but deterministic; the cold path cost is irrelevant),
// then overwrites the speculative outputs grid-stride.
// Hot path: a flag read + return on a small grid (~1 us).
// ============================================================
__global__ __launch_bounds__(128)
void nll_general_kernel(const float* __restrict__ samples,
                        const float* __restrict__ Phi,
                        const float* __restrict__ mu,
                        const float* __restrict__ Sigma,
                        float* __restrict__ out, int N) {
    if (g_notident == 0) return;

    __shared__ float A[64][129];   // augmented [Sigma | I], padded stride
    __shared__ float fcol[64];
    __shared__ float s_det;
    __shared__ int   s_piv;

    const int tid = threadIdx.x;
    const int bd  = blockDim.x;

    if (tid == 0) s_det = 1.0f;

    for (int i = tid; i < 64 * 64; i += bd) {
        int r = i >> 6, cc = i & 63;
        A[r][cc]      = Sigma[i];
        A[r][64 + cc] = (r == cc) ? 1.0f : 0.0f;
    }
    __syncthreads();

    for (int k = 0; k < 64; k++) {
        if (tid == 0) {
            int   p  = k;
            float mx = fabsf(A[k][k]);
            for (int i = k + 1; i < 64; i++) {
                float v = fabsf(A[i][k]);
                if (v > mx) { mx = v; p = i; }
            }
            s_piv = p;
        }
        __syncthreads();
        const int p = s_piv;
        if (p != k) {
            for (int cc = tid; cc < 128; cc += bd) {
                float t = A[k][cc]; A[k][cc] = A[p][cc]; A[p][cc] = t;
            }
        }
        __syncthreads();
        const float piv = A[k][k];
        if (tid == 0) s_det *= (p != k) ? -piv : piv;
        const float rpiv = 1.0f / piv;
        for (int cc = tid; cc < 128; cc += bd) A[k][cc] *= rpiv;
        __syncthreads();
        for (int r = tid; r < 64; r += bd) fcol[r] = A[r][k];
        __syncthreads();
        for (int idx = tid; idx < 64 * 128; idx += bd) {
            int r = idx >> 7, cc = idx & 127;
            if (r != k) A[r][cc] -= fcol[r] * A[k][cc];
        }
        __syncthreads();
    }

    const float det = s_det;
    const float c   = Phi[0] / sqrtf(TWO_PI_F * det);

    for (int n = blockIdx.x * blockDim.x + threadIdx.x; n < N;
         n += gridDim.x * blockDim.x) {
        float dv[64];
        #pragma unroll
        for (int i = 0; i < 64; i++) dv[i] = samples[n * 64 + i] - mu[i];
        float q = 0.0f;
        for (int r = 0; r < 64; r++) {
            float t = 0.0f;
            #pragma unroll
            for (int cc = 0; cc < 64; cc++) t += A[r][64 + cc] * dv[cc];
            q += t * dv[r];
        }
        out[n] = -logf(c * expf(-0.5f * q) + EPS_F);
    }
}

extern "C" void kernel_launch(void* const* d_in, const int* in_sizes, int n_in,
                              void* d_out, int out_size) {
    const float* samples = (const float*)d_in[0];
    const float* Phi     = (const float*)d_in[1];
    const float* mu      = (const float*)d_in[2];
    const float* Sigma   = (const float*)d_in[3];
    float* out = (float*)d_out;

    const int N = out_size;  // number of samples

    // speculative fast path + distributed Sigma check:
    // 16 samples per warp, 8 warps per block => 128 samples/block
    const int samples_per_block = 16 * 8;
    const int blocks = (N + samples_per_block - 1) / samples_per_block;
    nll_identity_kernel<<<blocks, 256>>>(samples, Phi, mu, Sigma, out, N);

    // fused cold path (inverse + det + recompute); early-exits when Sigma == I
    nll_general_kernel<<<148, 128>>>(samples, Phi, mu, Sigma, out, N);
}